// round 14
// baseline (speedup 1.0000x reference)
#include <cuda_runtime.h>
#include <cstdint>

#define NFEAT 256
#define NHID 64
#define NEG_SLOPE 0.05f
#define MAX_N 100000
#define MAX_E 1600000
#define GBM 64              // rows per CTA
#define GBK 64              // k per chunk

// ---------------- device scratch (no allocation allowed) ----------------
__device__ float  g_Wh[(size_t)MAX_N * NHID];   // 25.6 MB
__device__ float  g_si[MAX_N];
__device__ float  g_sj[MAX_N];
__device__ float  g_hsum[MAX_N];                // written by edgeB: 1/sum(h)
__device__ float  g_h[MAX_E];                   // h in ORIGINAL edge order
__device__ int    g_idx64;
__device__ int    g_count[MAX_N];
__device__ int    g_start[MAX_N + 1];
__device__ int    g_cursor[MAX_N];
__device__ int    g_bsum[512];
__device__ int    g_boff[512];
__device__ float2 g_pack[MAX_E];                // {h, dst-as-bits} src-sorted

// ---------------- index helper: dtype-adaptive, clamped ----------------
__device__ __forceinline__ int load_idx(const void* ei, size_t pos, int is64, int M) {
    int v;
    if (is64) v = (int)((const long long*)ei)[pos];
    else      v = ((const int*)ei)[pos];
    v = v < 0 ? 0 : (v >= M ? M - 1 : v);
    return v;
}

// ---------------- detect edge_index dtype ----------------
__global__ void detect_kernel(const void* ei, int E, int M) {
    __shared__ int bad;
    if (threadIdx.x == 0) bad = 0;
    __syncthreads();
    const long long* p = (const long long*)ei;
    int stride = E / 4096 > 0 ? E / 4096 : 1;
    for (int i = threadIdx.x; i < 4096; i += blockDim.x) {
        size_t pos = (size_t)i * stride;
        if (pos < (size_t)E) {
            long long v = p[pos];
            if (v < 0 || v >= M) atomicOr(&bad, 1);
        }
    }
    __syncthreads();
    if (threadIdx.x == 0) g_idx64 = bad ? 0 : 1;
}

// ---------------- zero per-node edge counters ----------------
__global__ void zero_small_kernel(int M) {
    int i = blockIdx.x * blockDim.x + threadIdx.x;
    if (i < M) g_count[i] = 0;
}

// ---------------- histogram of src ----------------
__global__ void hist_kernel(const void* __restrict__ ei, int E, int M) {
    int e = blockIdx.x * blockDim.x + threadIdx.x;
    if (e >= E) return;
    int s = load_idx(ei, e, g_idx64, M);
    atomicAdd(&g_count[s], 1);
}

// ---------------- GEMM: uniform-B FFMA2, 1 row x 16 cols per lane -------
// CTA: 64 rows x 64 cols, 256 threads (8 warps = 2 rowgrp x 4 colgrp).
// B reads are warp-uniform -> LDS broadcast; A is 1 scalar LDS per k.
// ~55 regs -> 4 CTAs/SM = 32 warps; fma-pipe-bound by construction.
__global__ void __launch_bounds__(256) gemm_kernel(
        const float* __restrict__ x,
        const float* __restrict__ W,
        const float* __restrict__ aw,
        int M) {
    __shared__ float As[GBM][GBK + 1];   // [row][k], pad 65 -> conflict-free reads
    __shared__ float Bs[GBK][NHID];      // [k][n], uniform reads
    __shared__ float sp_si[4][GBM];
    __shared__ float sp_sj[4][GBM];

    const int tid  = threadIdx.x;
    const int lane = tid & 31;
    const int w    = tid >> 5;
    const int cg   = w & 3;              // col group: cols cg*16..+15
    const int rg   = w >> 2;             // row group: rows rg*32..+31
    const int row  = rg * 32 + lane;     // 0..63, this lane's row
    const int m0   = blockIdx.x * GBM;

    unsigned long long acc2[8];
#pragma unroll
    for (int c = 0; c < 8; c++) acc2[c] = 0ULL;

    for (int chunk = 0; chunk < 4; chunk++) {
        const int k0 = chunk * GBK;
        // ---- load A chunk: 64 rows x 64 k (coalesced LDG, scalar STS) ----
#pragma unroll
        for (int p = 0; p < 4; p++) {
            int idx = p * 256 + tid;         // 0..1023
            int r   = idx >> 4;              // 0..63
            int ks  = (idx & 15) * 4;        // 0..60
            int gm  = m0 + r;
            const float* src = x + (size_t)(gm < M ? gm : M - 1) * NFEAT + k0 + ks;
            float4 v = *(const float4*)src;
            As[r][ks + 0] = v.x;
            As[r][ks + 1] = v.y;
            As[r][ks + 2] = v.z;
            As[r][ks + 3] = v.w;
        }
        // ---- load B chunk: 64 k x 64 n (coalesced) ----
#pragma unroll
        for (int p = 0; p < 4; p++) {
            int idx = p * 256 + tid;
            int k   = idx >> 4;
            int n   = (idx & 15) * 4;
            *(float4*)&Bs[k][n] = *(const float4*)&W[(size_t)(k0 + k) * NHID + n];
        }
        __syncthreads();

        // ---- compute 64 k-steps ----
#pragma unroll 16
        for (int k = 0; k < GBK; k++) {
            float a = As[row][k];
            unsigned long long ap;
            asm("mov.b64 %0, {%1, %1};" : "=l"(ap) : "r"(__float_as_uint(a)));
            const float* bb = &Bs[k][cg * 16];
            ulonglong2 q0 = *(const ulonglong2*)(bb);
            ulonglong2 q1 = *(const ulonglong2*)(bb + 4);
            ulonglong2 q2 = *(const ulonglong2*)(bb + 8);
            ulonglong2 q3 = *(const ulonglong2*)(bb + 12);
            asm("fma.rn.f32x2 %0, %1, %2, %0;" : "+l"(acc2[0]) : "l"(ap), "l"(q0.x));
            asm("fma.rn.f32x2 %0, %1, %2, %0;" : "+l"(acc2[1]) : "l"(ap), "l"(q0.y));
            asm("fma.rn.f32x2 %0, %1, %2, %0;" : "+l"(acc2[2]) : "l"(ap), "l"(q1.x));
            asm("fma.rn.f32x2 %0, %1, %2, %0;" : "+l"(acc2[3]) : "l"(ap), "l"(q1.y));
            asm("fma.rn.f32x2 %0, %1, %2, %0;" : "+l"(acc2[4]) : "l"(ap), "l"(q2.x));
            asm("fma.rn.f32x2 %0, %1, %2, %0;" : "+l"(acc2[5]) : "l"(ap), "l"(q2.y));
            asm("fma.rn.f32x2 %0, %1, %2, %0;" : "+l"(acc2[6]) : "l"(ap), "l"(q3.x));
            asm("fma.rn.f32x2 %0, %1, %2, %0;" : "+l"(acc2[7]) : "l"(ap), "l"(q3.y));
        }
        __syncthreads();
    }

    // ---- epilogue: store Wh, partial scores, cross-warp reduce ----
    float v[16];
#pragma unroll
    for (int c = 0; c < 8; c++) {
        v[2 * c]     = __uint_as_float((unsigned)(acc2[c] & 0xffffffffULL));
        v[2 * c + 1] = __uint_as_float((unsigned)(acc2[c] >> 32));
    }
    const int grow = m0 + row;
    if (grow < M) {
        float* wh = &g_Wh[(size_t)grow * NHID + cg * 16];
        *(float4*)&wh[0]  = make_float4(v[0], v[1], v[2], v[3]);
        *(float4*)&wh[4]  = make_float4(v[4], v[5], v[6], v[7]);
        *(float4*)&wh[8]  = make_float4(v[8], v[9], v[10], v[11]);
        *(float4*)&wh[12] = make_float4(v[12], v[13], v[14], v[15]);
    }
    float si = 0.f, sj = 0.f;
#pragma unroll
    for (int c = 0; c < 16; c++) {
        si += v[c] * __ldg(&aw[cg * 16 + c]);
        sj += v[c] * __ldg(&aw[64 + cg * 16 + c]);
    }
    sp_si[cg][row] = si;
    sp_sj[cg][row] = sj;
    __syncthreads();
    if (tid < GBM) {
        int gr = m0 + tid;
        if (gr < M) {
            float S = sp_si[0][tid] + sp_si[1][tid] + sp_si[2][tid] + sp_si[3][tid];
            float T = sp_sj[0][tid] + sp_sj[1][tid] + sp_sj[2][tid] + sp_sj[3][tid];
            g_si[gr] = S;
            g_sj[gr] = T;
        }
    }
}

// ---------------- exclusive scan over g_count (3 kernels) ----------------
__global__ void scan1_kernel(int M) {
    __shared__ int sm[256];
    int tid = threadIdx.x;
    int i = blockIdx.x * 256 + tid;
    int c = (i < M) ? g_count[i] : 0;
    sm[tid] = c;
    __syncthreads();
#pragma unroll
    for (int off = 1; off < 256; off <<= 1) {
        int v = (tid >= off) ? sm[tid - off] : 0;
        __syncthreads();
        sm[tid] += v;
        __syncthreads();
    }
    if (i < M) g_start[i] = sm[tid] - c;
    if (tid == 255) g_bsum[blockIdx.x] = sm[255];
}

__global__ void scan2_kernel(int nb) {
    __shared__ int sm[512];
    int tid = threadIdx.x;
    int c = (tid < nb) ? g_bsum[tid] : 0;
    sm[tid] = c;
    __syncthreads();
#pragma unroll
    for (int off = 1; off < 512; off <<= 1) {
        int v = (tid >= off) ? sm[tid - off] : 0;
        __syncthreads();
        sm[tid] += v;
        __syncthreads();
    }
    g_boff[tid] = sm[tid] - c;
}

__global__ void scan3_kernel(int M, int E) {
    int i = blockIdx.x * 256 + threadIdx.x;
    if (i >= M) return;
    int v = g_start[i] + g_boff[blockIdx.x];
    g_start[i] = v;
    g_cursor[i] = v;
    if (i == M - 1) g_start[M] = E;
}

// ---------------- edge pass A: h + sorted pack ----------------
__global__ void edgeA_fused_kernel(const void* __restrict__ ei,
                                   const float* __restrict__ ab, int E, int M) {
    int e = blockIdx.x * blockDim.x + threadIdx.x;
    if (e >= E) return;
    const int is64 = g_idx64;
    int s = load_idx(ei, e, is64, M);
    int d = load_idx(ei, (size_t)E + e, is64, M);
    float sc = g_si[s] + g_sj[d] + __ldg(&ab[0]);
    float l  = sc > 0.f ? sc : NEG_SLOPE * sc;
    float h  = expf(l);
    g_h[e] = h;
    int pos = atomicAdd(&g_cursor[s], 1);
    g_pack[pos] = make_float2(h, __int_as_float(d));
}

// ---------------- edge pass B: CSR gather; h_sum folded in ----------------
__global__ void __launch_bounds__(256) edgeB_csr_kernel(
        float* __restrict__ out, int M) {
    int warp = (blockIdx.x * blockDim.x + threadIdx.x) >> 5;
    if (warp >= M) return;
    int lane = threadIdx.x & 31;
    int sub  = lane >> 4;
    int part = lane & 15;

    int start = g_start[warp];
    int end   = g_start[warp + 1];

    float4 acc = make_float4(0.f, 0.f, 0.f, 0.f);
    float  hs  = 0.f;
    for (int pos = start + sub; pos < end; pos += 2) {
        float2 p = g_pack[pos];
        int    d = __float_as_int(p.y);
        float  h = p.x;
        hs += h;
        float4 w = *(const float4*)&g_Wh[(size_t)d * NHID + part * 4];
        acc.x += h * w.x;
        acc.y += h * w.y;
        acc.z += h * w.z;
        acc.w += h * w.w;
    }
    acc.x += __shfl_down_sync(0xffffffffu, acc.x, 16);
    acc.y += __shfl_down_sync(0xffffffffu, acc.y, 16);
    acc.z += __shfl_down_sync(0xffffffffu, acc.z, 16);
    acc.w += __shfl_down_sync(0xffffffffu, acc.w, 16);
    hs    += __shfl_down_sync(0xffffffffu, hs,    16);
    if (sub == 0) {
        float rinv = hs > 0.f ? __frcp_rn(hs) : 0.f;
        *(float4*)&out[(size_t)warp * NHID + part * 4] =
            make_float4(acc.x * rinv, acc.y * rinv, acc.z * rinv, acc.w * rinv);
        if (part == 0) g_hsum[warp] = rinv;
    }
}

// ---------------- alpha in original edge order (after edgeB) ------------
__global__ void alpha_kernel(const void* __restrict__ ei,
                             float* __restrict__ alpha_out, int E, int M) {
    int e = blockIdx.x * blockDim.x + threadIdx.x;
    if (e >= E) return;
    int s = load_idx(ei, e, g_idx64, M);
    alpha_out[e] = g_h[e] * g_hsum[s];
}

// ---------------- launch ----------------
extern "C" void kernel_launch(void* const* d_in, const int* in_sizes, int n_in,
                              void* d_out, int out_size) {
    const float* x  = (const float*)d_in[0];
    const float* W  = (const float*)d_in[1];
    const float* aw = (const float*)d_in[2];
    const float* ab = (const float*)d_in[3];
    const void*  ei = d_in[4];

    const int M = in_sizes[0] / NFEAT;       // 100000
    const int E = in_sizes[4] / 2;           // 1600000

    float* out       = (float*)d_out;
    float* alpha_out = (out_size >= M * NHID + E) ? out + (size_t)M * NHID : nullptr;

    const int nb = (M + 255) / 256;          // scan blocks (<=512)

    // gemm stays at launch index 3 (ncu captures index 3)
    detect_kernel<<<1, 256>>>(ei, E, M);                          // 0
    zero_small_kernel<<<nb, 256>>>(M);                            // 1
    hist_kernel<<<(E + 255) / 256, 256>>>(ei, E, M);              // 2
    gemm_kernel<<<(M + GBM - 1) / GBM, 256>>>(x, W, aw, M);       // 3 <- profiled
    scan1_kernel<<<nb, 256>>>(M);                                 // 4
    scan2_kernel<<<1, 512>>>(nb);                                 // 5
    scan3_kernel<<<nb, 256>>>(M, E);                              // 6
    edgeA_fused_kernel<<<(E + 255) / 256, 256>>>(ei, ab, E, M);   // 7
    edgeB_csr_kernel<<<(M * 32 + 255) / 256, 256>>>(out, M);      // 8
    if (alpha_out)
        alpha_kernel<<<(E + 255) / 256, 256>>>(ei, alpha_out, E, M); // 9
}